// round 11
// baseline (speedup 1.0000x reference)
#include <cuda_runtime.h>
#include <cuda_fp16.h>
#include <cstdint>

#define D     256
#define S     2048
#define BATCH 8
#define M_TOTAL (BATCH * S)   // 16384
#define KC    (3 * D)         // 768
#define PART  64

#define NCHUNK 12                 // K chunks of 64
#define ACH    16384              // A chunk: 128x64 fp16 (swizzled)
#define BCH    32768              // B chunk: 256x64 fp16 (swizzled)
#define MTILES (M_TOTAL / 128)    // 128
#define STAGE_BYTES (ACH + BCH)   // 49152
#define NSTAGE 4
#define GEMM_SMEM (NSTAGE * STAGE_BYTES)  // 196608

// ---------------- scratch (static device globals) ----------------
__device__ float g_part[BATCH][PART][D];
__device__ float g_total[BATCH][D];
__device__ __align__(16) unsigned char g_A[(size_t)MTILES * NCHUNK * ACH];  // 24 MB
__device__ __align__(16) unsigned char g_B[(size_t)NCHUNK * BCH];           // 384 KB

// ---------------- helpers ----------------
__device__ __forceinline__ uint32_t smem_u32(const void* p) {
    uint32_t a;
    asm("{ .reg .u64 t; cvta.to.shared.u64 t, %1; cvt.u32.u64 %0, t; }" : "=r"(a) : "l"(p));
    return a;
}
__device__ __forceinline__ uint32_t swoff(int row, int kk) {
    return (uint32_t)(row * 128 + ((((kk >> 3) ^ (row & 7)) << 4)) + (kk & 7) * 2);
}
__device__ __forceinline__ void cp16(uint32_t dst, const void* src) {
    asm volatile("cp.async.cg.shared.global [%0], [%1], 16;"
        :: "r"(dst), "l"(__cvta_generic_to_global(src)));
}
__device__ __forceinline__ void ldm_x4(uint32_t addr, uint32_t* f) {
    asm volatile("ldmatrix.sync.aligned.m8n8.x4.shared.b16 {%0,%1,%2,%3}, [%4];"
        : "=r"(f[0]), "=r"(f[1]), "=r"(f[2]), "=r"(f[3]) : "r"(addr));
}
__device__ __forceinline__ uint32_t a_addr(uint32_t base, int r0, int k0, int lane) {
    int i = lane & 7, seg = lane >> 3;
    int row = r0 + i + ((seg & 1) << 3);
    int kk = k0 + ((seg >> 1) << 3);
    return base + (uint32_t)(row * 128) + ((((kk >> 3) ^ (row & 7)) << 4));
}
__device__ __forceinline__ uint32_t b_addr(uint32_t base, int n0, int k0, int lane) {
    int i = lane & 7, seg = lane >> 3;
    int row = n0 + i + ((seg >> 1) << 3);
    int kk = k0 + ((seg & 1) << 3);
    return base + (uint32_t)(row * 128) + ((((kk >> 3) ^ (row & 7)) << 4));
}
__device__ __forceinline__ void mma16816(float* c, const uint32_t* a, uint32_t b0, uint32_t b1) {
    asm volatile("mma.sync.aligned.m16n8k16.row.col.f32.f16.f16.f32 "
        "{%0,%1,%2,%3}, {%4,%5,%6,%7}, {%8,%9}, {%0,%1,%2,%3};"
        : "+f"(c[0]), "+f"(c[1]), "+f"(c[2]), "+f"(c[3])
        : "r"(a[0]), "r"(a[1]), "r"(a[2]), "r"(a[3]), "r"(b0), "r"(b1));
}
__device__ __forceinline__ uint2 pack_half4(const float* v) {
    __half2 lo = __floats2half2_rn(v[0], v[1]);
    __half2 hi = __floats2half2_rn(v[2], v[3]);
    uint2 u;
    u.x = *(const uint32_t*)&lo;
    u.y = *(const uint32_t*)&hi;
    return u;
}

// ---------------------------------------------------------------------------
// Kernel 1: column sums stage 1 (two-stage, deterministic, float4, PART=64)
// ---------------------------------------------------------------------------
__global__ void __launch_bounds__(128)
colsum_part(const float* __restrict__ x) {
    int b = blockIdx.x, p = blockIdx.y, tid = threadIdx.x;
    int c4 = (tid & 63) * 4;
    int rh = tid >> 6;
    const int chunk = S / PART;    // 32
    const int half = chunk / 2;    // 16
    const float* xp = x + ((long)b * S + (long)(p * chunk + rh * half)) * D + c4;
    float a0 = 0.f, a1 = 0.f, a2 = 0.f, a3 = 0.f;
    #pragma unroll 8
    for (int s = 0; s < half; ++s) {
        float4 v = *(const float4*)(xp + (long)s * D);
        a0 += v.x; a1 += v.y; a2 += v.z; a3 += v.w;
    }
    __shared__ float4 sh[64];
    if (rh == 1) sh[tid & 63] = make_float4(a0, a1, a2, a3);
    __syncthreads();
    if (rh == 0) {
        float4 o = sh[tid & 63];
        *(float4*)(&g_part[b][p][c4]) = make_float4(a0 + o.x, a1 + o.y, a2 + o.z, a3 + o.w);
    }
}

// ---------------------------------------------------------------------------
// Kernel 2: colsum stage 2 + BOUNDARY z rows (t in [0,3] and [S-4,S-1])
// grid BATCH, 64 threads. Boundary math = R10 slow path, bit-identical.
// ---------------------------------------------------------------------------
__global__ void __launch_bounds__(64)
colsum_reduce_boundary(const float* __restrict__ x, const float* __restrict__ comp) {
    int b = blockIdx.x, tid = threadIdx.x;
    int c4 = tid * 4;
    float a0 = 0.f, a1 = 0.f, a2 = 0.f, a3 = 0.f;
    #pragma unroll
    for (int p = 0; p < PART; ++p) {
        float4 v = *(const float4*)(&g_part[b][p][c4]);
        a0 += v.x; a1 += v.y; a2 += v.z; a3 += v.w;
    }
    *(float4*)(&g_total[b][c4]) = make_float4(a0, a1, a2, a3);
    float tot[4] = {a0, a1, a2, a3};

    const float* xb = x + (size_t)b * S * D;
    float c00 = comp[0], c10 = comp[2], c20 = comp[4], c30 = comp[6];
    float c01 = comp[1], c11 = comp[3], c21 = comp[5], c31 = comp[7];
    int ch = c4 >> 6, kk = c4 & 63;

    #pragma unroll
    for (int side = 0; side < 2; ++side) {
        #pragma unroll
        for (int it = 0; it < 4; ++it) {
            int t = side ? (S - 4 + it) : it;
            bool pm1 = (t >= 1), pp1 = (t + 1 < S), pp2 = (t + 2 < S), pp3 = (t + 3 < S);
            float inv1 = 1.f / (1.f + (float)pp2);
            int n2i = (int)pm1 + (int)pp3;
            float inv2 = n2i ? 1.f / (float)n2i : 0.f;
            float inv3 = 1.f / (float)(S - (1 + (int)pm1 + (int)pp1 + (int)pp2 + (int)pp3));

            float4 zz = make_float4(0.f, 0.f, 0.f, 0.f);
            const float* p = xb + (size_t)t * D + c4;
            float4 tm1 = pm1 ? *(const float4*)(p - D)     : zz;
            float4 t00 =       *(const float4*)(p);
            float4 tp1 = pp1 ? *(const float4*)(p + D)     : zz;
            float4 tp2 = pp2 ? *(const float4*)(p + 2 * D) : zz;
            float4 tp3 = pp3 ? *(const float4*)(p + 3 * D) : zz;
            float xm1[4] = {tm1.x, tm1.y, tm1.z, tm1.w};
            float x00[4] = {t00.x, t00.y, t00.z, t00.w};
            float xp1[4] = {tp1.x, tp1.y, tp1.z, tp1.w};
            float xp2[4] = {tp2.x, tp2.y, tp2.z, tp2.w};
            float xp3[4] = {tp3.x, tp3.y, tp3.z, tp3.w};
            float z0[4], z1[4];
            #pragma unroll
            for (int j = 0; j < 4; ++j) {
                float wsum = xm1[j] + x00[j] + xp1[j] + xp2[j] + xp3[j];
                float aa0 = xp1[j];
                float aa1 = (x00[j] + xp2[j]) * inv1;
                float aa2 = (xm1[j] + xp3[j]) * inv2;
                float aa3 = (tot[j] - wsum) * inv3;
                z0[j] = c00 * aa0 + c10 * aa1 + c20 * aa2 + c30 * aa3;
                z1[j] = c01 * aa0 + c11 * aa1 + c21 * aa2 + c31 * aa3;
            }
            int m = b * S + t;
            unsigned char* tb = g_A + (size_t)((m >> 7) * NCHUNK) * ACH;
            uint32_t o = swoff(m & 127, kk);
            *(uint2*)(tb + (size_t)ch * ACH + o)       = pack_half4(z0);
            *(uint2*)(tb + (size_t)(ch + 4) * ACH + o) = pack_half4(z1);
            *(uint2*)(tb + (size_t)(ch + 8) * ACH + o) = pack_half4(x00);
        }
    }
}

// ---------------------------------------------------------------------------
// Kernel 3: build z interior (t in [4, S-5]), fast path ONLY: no masks, no
// divides. Boundary thread-groups early-return (handled by kernel 2).
// grid (S/16, BATCH), 256 threads, 4 t-rows/thread. Bit-identical numerics.
// ---------------------------------------------------------------------------
__global__ void __launch_bounds__(256)
build_z_pack(const float* __restrict__ x, const float* __restrict__ comp) {
    int b = blockIdx.y, tid = threadIdx.x;
    int t0 = blockIdx.x * 16;
    int i = (tid & 63) * 4;           // channel base
    int tbase = t0 + (tid >> 6) * 4;  // first of 4 t-rows for this thread
    if (tbase < 1 || tbase > S - 7) return;   // boundary groups done elsewhere

    const float* xb = x + (size_t)b * S * D;
    float c00 = comp[0], c10 = comp[2], c20 = comp[4], c30 = comp[6];
    float c01 = comp[1], c11 = comp[3], c21 = comp[5], c31 = comp[7];

    float4 tt4 = *(const float4*)(&g_total[b][i]);
    float tot[4] = {tt4.x, tt4.y, tt4.z, tt4.w};

    int mtile = (b * S + t0) >> 7;
    unsigned char* tb = g_A + (size_t)(mtile * NCHUNK) * ACH;
    int ch = i >> 6, kk = i & 63;

    const float inv1 = 0.5f;
    const float inv2 = 0.5f;
    const float inv3 = 1.0f / (float)(S - 5);

    float4 w[5];
    #pragma unroll
    for (int j = 0; j < 5; ++j)
        w[j] = *(const float4*)(xb + (size_t)(tbase - 1 + j) * D + i);

    #pragma unroll
    for (int it = 0; it < 4; ++it) {
        int t = tbase + it;
        float xm1[4] = {w[0].x, w[0].y, w[0].z, w[0].w};
        float x00[4] = {w[1].x, w[1].y, w[1].z, w[1].w};
        float xp1[4] = {w[2].x, w[2].y, w[2].z, w[2].w};
        float xp2[4] = {w[3].x, w[3].y, w[3].z, w[3].w};
        float xp3[4] = {w[4].x, w[4].y, w[4].z, w[4].w};
        float z0[4], z1[4];
        #pragma unroll
        for (int j = 0; j < 4; ++j) {
            float wsum = xm1[j] + x00[j] + xp1[j] + xp2[j] + xp3[j];
            float a0 = xp1[j];
            float a1 = (x00[j] + xp2[j]) * inv1;
            float a2 = (xm1[j] + xp3[j]) * inv2;
            float a3 = (tot[j] - wsum) * inv3;
            z0[j] = c00 * a0 + c10 * a1 + c20 * a2 + c30 * a3;
            z1[j] = c01 * a0 + c11 * a1 + c21 * a2 + c31 * a3;
        }
        int r = (b * S + t) & 127;
        uint32_t o = swoff(r, kk);
        *(uint2*)(tb + (size_t)ch * ACH + o)       = pack_half4(z0);
        *(uint2*)(tb + (size_t)(ch + 4) * ACH + o) = pack_half4(z1);
        *(uint2*)(tb + (size_t)(ch + 8) * ACH + o) = pack_half4(x00);
        if (it < 3) {
            w[0] = w[1]; w[1] = w[2]; w[2] = w[3]; w[3] = w[4];
            w[4] = *(const float4*)(xb + (size_t)(t + 4) * D + i);
        }
    }
}

// ---------------------------------------------------------------------------
// Kernel 4: pack weights W[k][n] -> g_B[chunk][n 256][k 64], fp16, swizzled
// ---------------------------------------------------------------------------
__global__ void convert_w(const float* __restrict__ basis, const float* __restrict__ root) {
    int k = blockIdx.x;          // 0..767
    int n = threadIdx.x;         // 0..255
    float v = (k < 2 * D) ? basis[(size_t)k * D + n] : root[(size_t)(k - 2 * D) * D + n];
    int chunk = k >> 6, kk = k & 63;
    *(__half*)(g_B + (size_t)chunk * BCH + swoff(n, kk)) = __float2half_rn(v);
}

// ---------------------------------------------------------------------------
// Kernel 5: HMMA GEMM  out[16384,256] = z @ W + bias  (1 pass, 4 stages)
// grid 128 (mtile), 512 threads, CTA tile 128x256, warp tile 32x64, BK=64
// ---------------------------------------------------------------------------
__device__ __forceinline__ void load_stage(uint32_t s, const unsigned char* A,
                                           const unsigned char* B, int tid) {
    uint32_t off = (uint32_t)tid * 16;
    cp16(s + off, A + off);
    cp16(s + 8192 + off, A + 8192 + off);
    #pragma unroll
    for (int i = 0; i < 4; ++i)
        cp16(s + ACH + off + (uint32_t)i * 8192, B + off + (uint32_t)i * 8192);
}

__global__ void __launch_bounds__(512, 1)
gemm_hmma(const float* __restrict__ bias, float* __restrict__ out) {
    extern __shared__ unsigned char smem[];
    uint32_t sbase = smem_u32(smem);
    int tid = threadIdx.x, lane = tid & 31, wid = tid >> 5;
    int wm = wid >> 2, wn = wid & 3;      // 4x4 warp grid; warp tile 32 x 64
    int mtile = blockIdx.x;

    const unsigned char* Asrc = g_A + (size_t)(mtile * NCHUNK) * ACH;

    #pragma unroll
    for (int s = 0; s < NSTAGE - 1; ++s) {
        load_stage(sbase + (uint32_t)s * STAGE_BYTES,
                   Asrc + (size_t)s * ACH, g_B + (size_t)s * BCH, tid);
        asm volatile("cp.async.commit_group;");
    }

    float acc[2][8][4];
    #pragma unroll
    for (int mt = 0; mt < 2; ++mt)
        #pragma unroll
        for (int nt = 0; nt < 8; ++nt)
            #pragma unroll
            for (int q = 0; q < 4; ++q) acc[mt][nt][q] = 0.f;

    for (int c = 0; c < NCHUNK; ++c) {
        if (c + NSTAGE - 1 < NCHUNK) {
            int cn = c + NSTAGE - 1;
            load_stage(sbase + (uint32_t)(cn & (NSTAGE - 1)) * STAGE_BYTES,
                       Asrc + (size_t)cn * ACH, g_B + (size_t)cn * BCH, tid);
            asm volatile("cp.async.commit_group;");
        }
        if (c <= NCHUNK - NSTAGE)      asm volatile("cp.async.wait_group 3;");
        else if (c == NCHUNK - 3)      asm volatile("cp.async.wait_group 2;");
        else if (c == NCHUNK - 2)      asm volatile("cp.async.wait_group 1;");
        else                           asm volatile("cp.async.wait_group 0;");
        __syncthreads();

        uint32_t st = sbase + (uint32_t)(c & (NSTAGE - 1)) * STAGE_BYTES;
        uint32_t Ah = st, Bh = st + ACH;

        #pragma unroll
        for (int k16 = 0; k16 < 4; ++k16) {
            int k0 = k16 * 16;
            uint32_t ah[2][4];
            #pragma unroll
            for (int mt = 0; mt < 2; ++mt)
                ldm_x4(a_addr(Ah, wm * 32 + mt * 16, k0, lane), ah[mt]);
            #pragma unroll
            for (int g = 0; g < 4; ++g) {
                uint32_t bh[4];
                ldm_x4(b_addr(Bh, wn * 64 + g * 16, k0, lane), bh);
                #pragma unroll
                for (int mt = 0; mt < 2; ++mt) {
                    mma16816(acc[mt][2 * g],     ah[mt], bh[0], bh[1]);
                    mma16816(acc[mt][2 * g + 1], ah[mt], bh[2], bh[3]);
                }
            }
        }
        __syncthreads();
    }

    // epilogue: bias + store
    int rbase = mtile * 128 + wm * 32 + (lane >> 2);
    int cbase = wn * 64 + (lane & 3) * 2;
    #pragma unroll
    for (int mt = 0; mt < 2; ++mt) {
        #pragma unroll
        for (int nt = 0; nt < 8; ++nt) {
            int row = rbase + mt * 16;
            int col = cbase + nt * 8;
            float b0 = bias[col], b1 = bias[col + 1];
            float2 v;
            v.x = acc[mt][nt][0] + b0; v.y = acc[mt][nt][1] + b1;
            *(float2*)(out + (size_t)row * D + col) = v;
            v.x = acc[mt][nt][2] + b0; v.y = acc[mt][nt][3] + b1;
            *(float2*)(out + (size_t)(row + 8) * D + col) = v;
        }
    }
}

// ---------------------------------------------------------------------------
extern "C" void kernel_launch(void* const* d_in, const int* in_sizes, int n_in,
                              void* d_out, int out_size) {
    const float* x     = (const float*)d_in[0];
    const float* comp  = (const float*)d_in[1];
    const float* basis = (const float*)d_in[2];
    const float* root  = (const float*)d_in[3];
    const float* bias  = (const float*)d_in[4];
    float* out = (float*)d_out;

    cudaFuncSetAttribute(gemm_hmma, cudaFuncAttributeMaxDynamicSharedMemorySize, GEMM_SMEM);

    convert_w<<<KC, D>>>(basis, root);
    colsum_part<<<dim3(BATCH, PART), 128>>>(x);
    colsum_reduce_boundary<<<BATCH, 64>>>(x, comp);
    build_z_pack<<<dim3(S / 16, BATCH), 256>>>(x, comp);
    gemm_hmma<<<MTILES, 512, GEMM_SMEM>>>(bias, out);
}

// round 12
// speedup vs baseline: 1.0386x; 1.0386x over previous
#include <cuda_runtime.h>
#include <cuda_fp16.h>
#include <cstdint>

#define D     256
#define S     2048
#define BATCH 8
#define M_TOTAL (BATCH * S)   // 16384
#define KC    (3 * D)         // 768
#define PART  64

#define NCHUNK 12                 // K chunks of 64
#define ACH    16384              // A chunk: 128x64 fp16 (swizzled)
#define BCH    32768              // B chunk: 256x64 fp16 (swizzled)
#define MTILES (M_TOTAL / 128)    // 128
#define STAGE_BYTES (ACH + BCH)   // 49152
#define NSTAGE 4
#define GEMM_SMEM (NSTAGE * STAGE_BYTES)  // 196608

// ---------------- scratch (static device globals) ----------------
__device__ float g_part[BATCH][PART][D];
__device__ float g_total[BATCH][D];
__device__ __align__(16) unsigned char g_A[(size_t)MTILES * NCHUNK * ACH];  // 24 MB
__device__ __align__(16) unsigned char g_B[(size_t)NCHUNK * BCH];           // 384 KB

// ---------------- helpers ----------------
__device__ __forceinline__ uint32_t smem_u32(const void* p) {
    uint32_t a;
    asm("{ .reg .u64 t; cvta.to.shared.u64 t, %1; cvt.u32.u64 %0, t; }" : "=r"(a) : "l"(p));
    return a;
}
__device__ __forceinline__ uint32_t swoff(int row, int kk) {
    return (uint32_t)(row * 128 + ((((kk >> 3) ^ (row & 7)) << 4)) + (kk & 7) * 2);
}
__device__ __forceinline__ void cp16(uint32_t dst, const void* src) {
    asm volatile("cp.async.cg.shared.global [%0], [%1], 16;"
        :: "r"(dst), "l"(__cvta_generic_to_global(src)));
}
__device__ __forceinline__ void ldm_x4(uint32_t addr, uint32_t* f) {
    asm volatile("ldmatrix.sync.aligned.m8n8.x4.shared.b16 {%0,%1,%2,%3}, [%4];"
        : "=r"(f[0]), "=r"(f[1]), "=r"(f[2]), "=r"(f[3]) : "r"(addr));
}
__device__ __forceinline__ uint32_t a_addr(uint32_t base, int r0, int k0, int lane) {
    int i = lane & 7, seg = lane >> 3;
    int row = r0 + i + ((seg & 1) << 3);
    int kk = k0 + ((seg >> 1) << 3);
    return base + (uint32_t)(row * 128) + ((((kk >> 3) ^ (row & 7)) << 4));
}
__device__ __forceinline__ uint32_t b_addr(uint32_t base, int n0, int k0, int lane) {
    int i = lane & 7, seg = lane >> 3;
    int row = n0 + i + ((seg >> 1) << 3);
    int kk = k0 + ((seg & 1) << 3);
    return base + (uint32_t)(row * 128) + ((((kk >> 3) ^ (row & 7)) << 4));
}
__device__ __forceinline__ void mma16816(float* c, const uint32_t* a, uint32_t b0, uint32_t b1) {
    asm volatile("mma.sync.aligned.m16n8k16.row.col.f32.f16.f16.f32 "
        "{%0,%1,%2,%3}, {%4,%5,%6,%7}, {%8,%9}, {%0,%1,%2,%3};"
        : "+f"(c[0]), "+f"(c[1]), "+f"(c[2]), "+f"(c[3])
        : "r"(a[0]), "r"(a[1]), "r"(a[2]), "r"(a[3]), "r"(b0), "r"(b1));
}
__device__ __forceinline__ uint2 pack_half4(const float* v) {
    __half2 lo = __floats2half2_rn(v[0], v[1]);
    __half2 hi = __floats2half2_rn(v[2], v[3]);
    uint2 u;
    u.x = *(const uint32_t*)&lo;
    u.y = *(const uint32_t*)&hi;
    return u;
}

// ---------------------------------------------------------------------------
// Kernel 1: column sums (two-stage, deterministic, float4, PART=64)
// ---------------------------------------------------------------------------
__global__ void __launch_bounds__(128)
colsum_part(const float* __restrict__ x) {
    int b = blockIdx.x, p = blockIdx.y, tid = threadIdx.x;
    int c4 = (tid & 63) * 4;
    int rh = tid >> 6;
    const int chunk = S / PART;    // 32
    const int half = chunk / 2;    // 16
    const float* xp = x + ((long)b * S + (long)(p * chunk + rh * half)) * D + c4;
    float a0 = 0.f, a1 = 0.f, a2 = 0.f, a3 = 0.f;
    #pragma unroll 8
    for (int s = 0; s < half; ++s) {
        float4 v = *(const float4*)(xp + (long)s * D);
        a0 += v.x; a1 += v.y; a2 += v.z; a3 += v.w;
    }
    __shared__ float4 sh[64];
    if (rh == 1) sh[tid & 63] = make_float4(a0, a1, a2, a3);
    __syncthreads();
    if (rh == 0) {
        float4 o = sh[tid & 63];
        *(float4*)(&g_part[b][p][c4]) = make_float4(a0 + o.x, a1 + o.y, a2 + o.z, a3 + o.w);
    }
}
__global__ void __launch_bounds__(64)
colsum_reduce() {
    int b = blockIdx.x, c4 = threadIdx.x * 4;
    float a0 = 0.f, a1 = 0.f, a2 = 0.f, a3 = 0.f;
    #pragma unroll
    for (int p = 0; p < PART; ++p) {
        float4 v = *(const float4*)(&g_part[b][p][c4]);
        a0 += v.x; a1 += v.y; a2 += v.z; a3 += v.w;
    }
    *(float4*)(&g_total[b][c4]) = make_float4(a0, a1, a2, a3);
}

// ---------------------------------------------------------------------------
// Kernel 2: build z = [z0 | z1 | x], fp16, rolling 5-tap window, 4 t-rows/thread
// Interior fast path (t in [1, S-7]): no masks, no divides (constant inv).
// grid (S/16, BATCH), 256 threads. Numerics bit-identical to R5/R9/R10.
// ---------------------------------------------------------------------------
__global__ void __launch_bounds__(256)
build_z_pack(const float* __restrict__ x, const float* __restrict__ comp) {
    int b = blockIdx.y, tid = threadIdx.x;
    int t0 = blockIdx.x * 16;
    int i = (tid & 63) * 4;           // channel base
    int tbase = t0 + (tid >> 6) * 4;  // first of 4 t-rows for this thread
    const float* xb = x + (size_t)b * S * D;

    float c00 = comp[0], c10 = comp[2], c20 = comp[4], c30 = comp[6];
    float c01 = comp[1], c11 = comp[3], c21 = comp[5], c31 = comp[7];

    float4 tt4 = *(const float4*)(&g_total[b][i]);
    float tot[4] = {tt4.x, tt4.y, tt4.z, tt4.w};

    int mtile = (b * S + t0) >> 7;
    unsigned char* tb = g_A + (size_t)(mtile * NCHUNK) * ACH;
    int ch = i >> 6, kk = i & 63;

    if (tbase >= 1 && tbase <= S - 7) {
        const float inv1 = 0.5f;
        const float inv2 = 0.5f;
        const float inv3 = 1.0f / (float)(S - 5);

        float4 w[5];
        #pragma unroll
        for (int j = 0; j < 5; ++j)
            w[j] = *(const float4*)(xb + (size_t)(tbase - 1 + j) * D + i);

        #pragma unroll
        for (int it = 0; it < 4; ++it) {
            int t = tbase + it;
            float xm1[4] = {w[0].x, w[0].y, w[0].z, w[0].w};
            float x00[4] = {w[1].x, w[1].y, w[1].z, w[1].w};
            float xp1[4] = {w[2].x, w[2].y, w[2].z, w[2].w};
            float xp2[4] = {w[3].x, w[3].y, w[3].z, w[3].w};
            float xp3[4] = {w[4].x, w[4].y, w[4].z, w[4].w};
            float z0[4], z1[4];
            #pragma unroll
            for (int j = 0; j < 4; ++j) {
                float wsum = xm1[j] + x00[j] + xp1[j] + xp2[j] + xp3[j];
                float a0 = xp1[j];
                float a1 = (x00[j] + xp2[j]) * inv1;
                float a2 = (xm1[j] + xp3[j]) * inv2;
                float a3 = (tot[j] - wsum) * inv3;
                z0[j] = c00 * a0 + c10 * a1 + c20 * a2 + c30 * a3;
                z1[j] = c01 * a0 + c11 * a1 + c21 * a2 + c31 * a3;
            }
            int r = (b * S + t) & 127;
            uint32_t o = swoff(r, kk);
            *(uint2*)(tb + (size_t)ch * ACH + o)       = pack_half4(z0);
            *(uint2*)(tb + (size_t)(ch + 4) * ACH + o) = pack_half4(z1);
            *(uint2*)(tb + (size_t)(ch + 8) * ACH + o) = pack_half4(x00);
            if (it < 3) {
                w[0] = w[1]; w[1] = w[2]; w[2] = w[3]; w[3] = w[4];
                w[4] = *(const float4*)(xb + (size_t)(t + 4) * D + i);
            }
        }
    } else {
        float4 w[5];
        #pragma unroll
        for (int j = 0; j < 5; ++j) {
            int row = tbase - 1 + j;
            w[j] = (row >= 0 && row < S) ? *(const float4*)(xb + (size_t)row * D + i)
                                         : make_float4(0.f, 0.f, 0.f, 0.f);
        }
        #pragma unroll
        for (int it = 0; it < 4; ++it) {
            int t = tbase + it;
            bool pm1 = (t >= 1), pp1 = (t + 1 < S), pp2 = (t + 2 < S), pp3 = (t + 3 < S);
            float inv1 = 1.f / (1.f + (float)pp2);
            int n2i = (int)pm1 + (int)pp3;
            float inv2 = n2i ? 1.f / (float)n2i : 0.f;
            float inv3 = 1.f / (float)(S - (1 + (int)pm1 + (int)pp1 + (int)pp2 + (int)pp3));

            float xm1[4] = {w[0].x, w[0].y, w[0].z, w[0].w};
            float x00[4] = {w[1].x, w[1].y, w[1].z, w[1].w};
            float xp1[4] = {w[2].x, w[2].y, w[2].z, w[2].w};
            float xp2[4] = {w[3].x, w[3].y, w[3].z, w[3].w};
            float xp3[4] = {w[4].x, w[4].y, w[4].z, w[4].w};
            float z0[4], z1[4];
            #pragma unroll
            for (int j = 0; j < 4; ++j) {
                float wsum = xm1[j] + x00[j] + xp1[j] + xp2[j] + xp3[j];
                float a0 = xp1[j];
                float a1 = (x00[j] + xp2[j]) * inv1;
                float a2 = (xm1[j] + xp3[j]) * inv2;
                float a3 = (tot[j] - wsum) * inv3;
                z0[j] = c00 * a0 + c10 * a1 + c20 * a2 + c30 * a3;
                z1[j] = c01 * a0 + c11 * a1 + c21 * a2 + c31 * a3;
            }
            int r = (b * S + t) & 127;
            uint32_t o = swoff(r, kk);
            *(uint2*)(tb + (size_t)ch * ACH + o)       = pack_half4(z0);
            *(uint2*)(tb + (size_t)(ch + 4) * ACH + o) = pack_half4(z1);
            *(uint2*)(tb + (size_t)(ch + 8) * ACH + o) = pack_half4(x00);
            if (it < 3) {
                w[0] = w[1]; w[1] = w[2]; w[2] = w[3]; w[3] = w[4];
                int row = t + 4;
                w[4] = (row < S) ? *(const float4*)(xb + (size_t)row * D + i)
                                 : make_float4(0.f, 0.f, 0.f, 0.f);
            }
        }
    }
}

// ---------------------------------------------------------------------------
// Kernel 3: pack weights W[k][n] -> g_B[chunk][n 256][k 64], fp16, swizzled
// ---------------------------------------------------------------------------
__global__ void convert_w(const float* __restrict__ basis, const float* __restrict__ root) {
    int k = blockIdx.x;          // 0..767
    int n = threadIdx.x;         // 0..255
    float v = (k < 2 * D) ? basis[(size_t)k * D + n] : root[(size_t)(k - 2 * D) * D + n];
    int chunk = k >> 6, kk = k & 63;
    *(__half*)(g_B + (size_t)chunk * BCH + swoff(n, kk)) = __float2half_rn(v);
}

// ---------------------------------------------------------------------------
// Kernel 4: HMMA GEMM  out[16384,256] = z @ W + bias  (1 pass, 4 stages)
// grid 128 (mtile), 256 threads, CTA tile 128x256, 8 warps 2x4, warp tile 64x64
// 8 ldmatrix per 32 MMAs per k16 (1.5x less smem read than 16-warp 32x64).
// ---------------------------------------------------------------------------
__device__ __forceinline__ void load_stage(uint32_t s, const unsigned char* A,
                                           const unsigned char* B, int tid) {
    uint32_t off = (uint32_t)tid * 16;
    #pragma unroll
    for (int i = 0; i < 4; ++i)
        cp16(s + off + (uint32_t)i * 4096, A + off + (uint32_t)i * 4096);
    #pragma unroll
    for (int i = 0; i < 8; ++i)
        cp16(s + ACH + off + (uint32_t)i * 4096, B + off + (uint32_t)i * 4096);
}

__global__ void __launch_bounds__(256, 1)
gemm_hmma(const float* __restrict__ bias, float* __restrict__ out) {
    extern __shared__ unsigned char smem[];
    uint32_t sbase = smem_u32(smem);
    int tid = threadIdx.x, lane = tid & 31, wid = tid >> 5;
    int wm = wid >> 2, wn = wid & 3;      // 2x4 warp grid; warp tile 64x64
    int mtile = blockIdx.x;

    const unsigned char* Asrc = g_A + (size_t)(mtile * NCHUNK) * ACH;

    #pragma unroll
    for (int s = 0; s < NSTAGE - 1; ++s) {
        load_stage(sbase + (uint32_t)s * STAGE_BYTES,
                   Asrc + (size_t)s * ACH, g_B + (size_t)s * BCH, tid);
        asm volatile("cp.async.commit_group;");
    }

    float acc[4][8][4];
    #pragma unroll
    for (int mt = 0; mt < 4; ++mt)
        #pragma unroll
        for (int nt = 0; nt < 8; ++nt)
            #pragma unroll
            for (int q = 0; q < 4; ++q) acc[mt][nt][q] = 0.f;

    for (int c = 0; c < NCHUNK; ++c) {
        if (c + NSTAGE - 1 < NCHUNK) {
            int cn = c + NSTAGE - 1;
            load_stage(sbase + (uint32_t)(cn & (NSTAGE - 1)) * STAGE_BYTES,
                       Asrc + (size_t)cn * ACH, g_B + (size_t)cn * BCH, tid);
            asm volatile("cp.async.commit_group;");
        }
        if (c <= NCHUNK - NSTAGE)      asm volatile("cp.async.wait_group 3;");
        else if (c == NCHUNK - 3)      asm volatile("cp.async.wait_group 2;");
        else if (c == NCHUNK - 2)      asm volatile("cp.async.wait_group 1;");
        else                           asm volatile("cp.async.wait_group 0;");
        __syncthreads();

        uint32_t st = sbase + (uint32_t)(c & (NSTAGE - 1)) * STAGE_BYTES;
        uint32_t Ah = st, Bh = st + ACH;

        #pragma unroll
        for (int k16 = 0; k16 < 4; ++k16) {
            int k0 = k16 * 16;
            uint32_t ah[4][4];
            #pragma unroll
            for (int mt = 0; mt < 4; ++mt)
                ldm_x4(a_addr(Ah, wm * 64 + mt * 16, k0, lane), ah[mt]);
            #pragma unroll
            for (int g = 0; g < 4; ++g) {
                uint32_t bh[4];
                ldm_x4(b_addr(Bh, wn * 64 + g * 16, k0, lane), bh);
                #pragma unroll
                for (int mt = 0; mt < 4; ++mt) {
                    mma16816(acc[mt][2 * g],     ah[mt], bh[0], bh[1]);
                    mma16816(acc[mt][2 * g + 1], ah[mt], bh[2], bh[3]);
                }
            }
        }
        __syncthreads();
    }

    // epilogue: bias + store
    int rbase = mtile * 128 + wm * 64 + (lane >> 2);
    int cbase = wn * 64 + (lane & 3) * 2;
    #pragma unroll
    for (int mt = 0; mt < 4; ++mt) {
        #pragma unroll
        for (int nt = 0; nt < 8; ++nt) {
            int row = rbase + mt * 16;
            int col = cbase + nt * 8;
            float b0 = bias[col], b1 = bias[col + 1];
            float2 v;
            v.x = acc[mt][nt][0] + b0; v.y = acc[mt][nt][1] + b1;
            *(float2*)(out + (size_t)row * D + col) = v;
            v.x = acc[mt][nt][2] + b0; v.y = acc[mt][nt][3] + b1;
            *(float2*)(out + (size_t)(row + 8) * D + col) = v;
        }
    }
}

// ---------------------------------------------------------------------------
extern "C" void kernel_launch(void* const* d_in, const int* in_sizes, int n_in,
                              void* d_out, int out_size) {
    const float* x     = (const float*)d_in[0];
    const float* comp  = (const float*)d_in[1];
    const float* basis = (const float*)d_in[2];
    const float* root  = (const float*)d_in[3];
    const float* bias  = (const float*)d_in[4];
    float* out = (float*)d_out;

    cudaFuncSetAttribute(gemm_hmma, cudaFuncAttributeMaxDynamicSharedMemorySize, GEMM_SMEM);

    convert_w<<<KC, D>>>(basis, root);
    colsum_part<<<dim3(BATCH, PART), 128>>>(x);
    colsum_reduce<<<BATCH, 64>>>();
    build_z_pack<<<dim3(S / 16, BATCH), 256>>>(x, comp);
    gemm_hmma<<<MTILES, 256, GEMM_SMEM>>>(bias, out);
}

// round 14
// speedup vs baseline: 1.0943x; 1.0537x over previous
#include <cuda_runtime.h>
#include <cuda_fp16.h>
#include <cstdint>

#define D     256
#define S     2048
#define BATCH 8
#define M_TOTAL (BATCH * S)   // 16384
#define KC    (3 * D)         // 768
#define PART  64

#define NCHUNK 12                 // K chunks of 64
#define ACH    16384              // A chunk: 128x64 fp16 (swizzled)
#define BCH    32768              // B chunk: 256x64 fp16 (swizzled)
#define MTILES (M_TOTAL / 128)    // 128
#define STAGE_BYTES (ACH + BCH)   // 49152
#define NSTAGE 4
#define GEMM_SMEM (NSTAGE * STAGE_BYTES)  // 196608

// ---------------- scratch (static device globals) ----------------
__device__ float g_part[BATCH][PART][D];
__device__ float g_total[BATCH][D];
__device__ __align__(16) unsigned char g_A[(size_t)MTILES * NCHUNK * ACH];  // 24 MB
__device__ __align__(16) unsigned char g_B[(size_t)NCHUNK * BCH];           // 384 KB

// ---------------- helpers ----------------
__device__ __forceinline__ uint32_t smem_u32(const void* p) {
    uint32_t a;
    asm("{ .reg .u64 t; cvta.to.shared.u64 t, %1; cvt.u32.u64 %0, t; }" : "=r"(a) : "l"(p));
    return a;
}
__device__ __forceinline__ uint32_t swoff(int row, int kk) {
    return (uint32_t)(row * 128 + ((((kk >> 3) ^ (row & 7)) << 4)) + (kk & 7) * 2);
}
__device__ __forceinline__ void cp16(uint32_t dst, const void* src) {
    asm volatile("cp.async.cg.shared.global [%0], [%1], 16;"
        :: "r"(dst), "l"(__cvta_generic_to_global(src)));
}
__device__ __forceinline__ void ldm_x4(uint32_t addr, uint32_t* f) {
    asm volatile("ldmatrix.sync.aligned.m8n8.x4.shared.b16 {%0,%1,%2,%3}, [%4];"
        : "=r"(f[0]), "=r"(f[1]), "=r"(f[2]), "=r"(f[3]) : "r"(addr));
}
__device__ __forceinline__ uint32_t a_addr(uint32_t base, int r0, int k0, int lane) {
    int i = lane & 7, seg = lane >> 3;
    int row = r0 + i + ((seg & 1) << 3);
    int kk = k0 + ((seg >> 1) << 3);
    return base + (uint32_t)(row * 128) + ((((kk >> 3) ^ (row & 7)) << 4));
}
__device__ __forceinline__ uint32_t b_addr(uint32_t base, int n0, int k0, int lane) {
    int i = lane & 7, seg = lane >> 3;
    int row = n0 + i + ((seg >> 1) << 3);
    int kk = k0 + ((seg & 1) << 3);
    return base + (uint32_t)(row * 128) + ((((kk >> 3) ^ (row & 7)) << 4));
}
__device__ __forceinline__ void mma16816(float* c, const uint32_t* a, uint32_t b0, uint32_t b1) {
    asm volatile("mma.sync.aligned.m16n8k16.row.col.f32.f16.f16.f32 "
        "{%0,%1,%2,%3}, {%4,%5,%6,%7}, {%8,%9}, {%0,%1,%2,%3};"
        : "+f"(c[0]), "+f"(c[1]), "+f"(c[2]), "+f"(c[3])
        : "r"(a[0]), "r"(a[1]), "r"(a[2]), "r"(a[3]), "r"(b0), "r"(b1));
}
__device__ __forceinline__ uint2 pack_half4(const float* v) {
    __half2 lo = __floats2half2_rn(v[0], v[1]);
    __half2 hi = __floats2half2_rn(v[2], v[3]);
    uint2 u;
    u.x = *(const uint32_t*)&lo;
    u.y = *(const uint32_t*)&hi;
    return u;
}

// ---------------------------------------------------------------------------
// Kernel 1: prep = colsum partials (blocks 0..511) + weight pack (512..1279)
// colsum blocks are short (16 rows/thread-half); convert blocks are tiny.
// ---------------------------------------------------------------------------
__global__ void __launch_bounds__(128)
prep(const float* __restrict__ x, const float* __restrict__ basis,
     const float* __restrict__ root) {
    int blk = blockIdx.x, tid = threadIdx.x;
    if (blk < BATCH * PART) {
        int b = blk >> 6, p = blk & 63;
        int c4 = (tid & 63) * 4;
        int rh = tid >> 6;
        const int chunk = S / PART;    // 32
        const int half = chunk / 2;    // 16
        const float* xp = x + ((long)b * S + (long)(p * chunk + rh * half)) * D + c4;
        float a0 = 0.f, a1 = 0.f, a2 = 0.f, a3 = 0.f;
        #pragma unroll 8
        for (int s = 0; s < half; ++s) {
            float4 v = *(const float4*)(xp + (long)s * D);
            a0 += v.x; a1 += v.y; a2 += v.z; a3 += v.w;
        }
        __shared__ float4 sh[64];
        if (rh == 1) sh[tid & 63] = make_float4(a0, a1, a2, a3);
        __syncthreads();
        if (rh == 0) {
            float4 o = sh[tid & 63];
            *(float4*)(&g_part[b][p][c4]) =
                make_float4(a0 + o.x, a1 + o.y, a2 + o.z, a3 + o.w);
        }
    } else {
        int k = blk - BATCH * PART;    // 0..767
        int chunk = k >> 6, kk = k & 63;
        unsigned char* blkp = g_B + (size_t)chunk * BCH;
        #pragma unroll
        for (int h = 0; h < 2; ++h) {
            int n = tid + h * 128;
            float v = (k < 2 * D) ? basis[(size_t)k * D + n]
                                  : root[(size_t)(k - 2 * D) * D + n];
            *(__half*)(blkp + swoff(n, kk)) = __float2half_rn(v);
        }
    }
}

__global__ void __launch_bounds__(64)
colsum_reduce() {
    int b = blockIdx.x, c4 = threadIdx.x * 4;
    float a0 = 0.f, a1 = 0.f, a2 = 0.f, a3 = 0.f;
    #pragma unroll
    for (int p = 0; p < PART; ++p) {
        float4 v = *(const float4*)(&g_part[b][p][c4]);
        a0 += v.x; a1 += v.y; a2 += v.z; a3 += v.w;
    }
    *(float4*)(&g_total[b][c4]) = make_float4(a0, a1, a2, a3);
}

// ---------------------------------------------------------------------------
// Kernel 2: build z = [z0 | z1 | x], fp16, rolling 5-tap window, 4 t-rows/thread
// Interior fast path; __launch_bounds__(256, 6) to lift occupancy (latency-bound).
// Numerics bit-identical to R5/R9/R10/R12.
// ---------------------------------------------------------------------------
__global__ void __launch_bounds__(256, 6)
build_z_pack(const float* __restrict__ x, const float* __restrict__ comp) {
    int b = blockIdx.y, tid = threadIdx.x;
    int t0 = blockIdx.x * 16;
    int i = (tid & 63) * 4;           // channel base
    int tbase = t0 + (tid >> 6) * 4;  // first of 4 t-rows for this thread
    const float* xb = x + (size_t)b * S * D;

    float c00 = comp[0], c10 = comp[2], c20 = comp[4], c30 = comp[6];
    float c01 = comp[1], c11 = comp[3], c21 = comp[5], c31 = comp[7];

    float4 tt4 = *(const float4*)(&g_total[b][i]);
    float tot[4] = {tt4.x, tt4.y, tt4.z, tt4.w};

    int mtile = (b * S + t0) >> 7;
    unsigned char* tb = g_A + (size_t)(mtile * NCHUNK) * ACH;
    int ch = i >> 6, kk = i & 63;

    if (tbase >= 1 && tbase <= S - 7) {
        const float inv1 = 0.5f;
        const float inv2 = 0.5f;
        const float inv3 = 1.0f / (float)(S - 5);

        float4 w[5];
        #pragma unroll
        for (int j = 0; j < 5; ++j)
            w[j] = *(const float4*)(xb + (size_t)(tbase - 1 + j) * D + i);

        #pragma unroll
        for (int it = 0; it < 4; ++it) {
            int t = tbase + it;
            float xm1[4] = {w[0].x, w[0].y, w[0].z, w[0].w};
            float x00[4] = {w[1].x, w[1].y, w[1].z, w[1].w};
            float xp1[4] = {w[2].x, w[2].y, w[2].z, w[2].w};
            float xp2[4] = {w[3].x, w[3].y, w[3].z, w[3].w};
            float xp3[4] = {w[4].x, w[4].y, w[4].z, w[4].w};
            float z0[4], z1[4];
            #pragma unroll
            for (int j = 0; j < 4; ++j) {
                float wsum = xm1[j] + x00[j] + xp1[j] + xp2[j] + xp3[j];
                float a0 = xp1[j];
                float a1 = (x00[j] + xp2[j]) * inv1;
                float a2 = (xm1[j] + xp3[j]) * inv2;
                float a3 = (tot[j] - wsum) * inv3;
                z0[j] = c00 * a0 + c10 * a1 + c20 * a2 + c30 * a3;
                z1[j] = c01 * a0 + c11 * a1 + c21 * a2 + c31 * a3;
            }
            int r = (b * S + t) & 127;
            uint32_t o = swoff(r, kk);
            *(uint2*)(tb + (size_t)ch * ACH + o)       = pack_half4(z0);
            *(uint2*)(tb + (size_t)(ch + 4) * ACH + o) = pack_half4(z1);
            *(uint2*)(tb + (size_t)(ch + 8) * ACH + o) = pack_half4(x00);
            if (it < 3) {
                w[0] = w[1]; w[1] = w[2]; w[2] = w[3]; w[3] = w[4];
                w[4] = *(const float4*)(xb + (size_t)(t + 4) * D + i);
            }
        }
    } else {
        float4 w[5];
        #pragma unroll
        for (int j = 0; j < 5; ++j) {
            int row = tbase - 1 + j;
            w[j] = (row >= 0 && row < S) ? *(const float4*)(xb + (size_t)row * D + i)
                                         : make_float4(0.f, 0.f, 0.f, 0.f);
        }
        #pragma unroll
        for (int it = 0; it < 4; ++it) {
            int t = tbase + it;
            bool pm1 = (t >= 1), pp1 = (t + 1 < S), pp2 = (t + 2 < S), pp3 = (t + 3 < S);
            float inv1 = 1.f / (1.f + (float)pp2);
            int n2i = (int)pm1 + (int)pp3;
            float inv2 = n2i ? 1.f / (float)n2i : 0.f;
            float inv3 = 1.f / (float)(S - (1 + (int)pm1 + (int)pp1 + (int)pp2 + (int)pp3));

            float xm1[4] = {w[0].x, w[0].y, w[0].z, w[0].w};
            float x00[4] = {w[1].x, w[1].y, w[1].z, w[1].w};
            float xp1[4] = {w[2].x, w[2].y, w[2].z, w[2].w};
            float xp2[4] = {w[3].x, w[3].y, w[3].z, w[3].w};
            float xp3[4] = {w[4].x, w[4].y, w[4].z, w[4].w};
            float z0[4], z1[4];
            #pragma unroll
            for (int j = 0; j < 4; ++j) {
                float wsum = xm1[j] + x00[j] + xp1[j] + xp2[j] + xp3[j];
                float a0 = xp1[j];
                float a1 = (x00[j] + xp2[j]) * inv1;
                float a2 = (xm1[j] + xp3[j]) * inv2;
                float a3 = (tot[j] - wsum) * inv3;
                z0[j] = c00 * a0 + c10 * a1 + c20 * a2 + c30 * a3;
                z1[j] = c01 * a0 + c11 * a1 + c21 * a2 + c31 * a3;
            }
            int r = (b * S + t) & 127;
            uint32_t o = swoff(r, kk);
            *(uint2*)(tb + (size_t)ch * ACH + o)       = pack_half4(z0);
            *(uint2*)(tb + (size_t)(ch + 4) * ACH + o) = pack_half4(z1);
            *(uint2*)(tb + (size_t)(ch + 8) * ACH + o) = pack_half4(x00);
            if (it < 3) {
                w[0] = w[1]; w[1] = w[2]; w[2] = w[3]; w[3] = w[4];
                int row = t + 4;
                w[4] = (row < S) ? *(const float4*)(xb + (size_t)row * D + i)
                                 : make_float4(0.f, 0.f, 0.f, 0.f);
            }
        }
    }
}

// ---------------------------------------------------------------------------
// Kernel 3: HMMA GEMM  out[16384,256] = z @ W + bias  (1 pass, 4 stages)
// grid 128 (mtile), 256 threads, CTA tile 128x256, 8 warps 2x4, warp tile 64x64
// ---------------------------------------------------------------------------
__device__ __forceinline__ void load_stage(uint32_t s, const unsigned char* A,
                                           const unsigned char* B, int tid) {
    uint32_t off = (uint32_t)tid * 16;
    #pragma unroll
    for (int i = 0; i < 4; ++i)
        cp16(s + off + (uint32_t)i * 4096, A + off + (uint32_t)i * 4096);
    #pragma unroll
    for (int i = 0; i < 8; ++i)
        cp16(s + ACH + off + (uint32_t)i * 4096, B + off + (uint32_t)i * 4096);
}

__global__ void __launch_bounds__(256, 1)
gemm_hmma(const float* __restrict__ bias, float* __restrict__ out) {
    extern __shared__ unsigned char smem[];
    uint32_t sbase = smem_u32(smem);
    int tid = threadIdx.x, lane = tid & 31, wid = tid >> 5;
    int wm = wid >> 2, wn = wid & 3;      // 2x4 warp grid; warp tile 64x64
    int mtile = blockIdx.x;

    const unsigned char* Asrc = g_A + (size_t)(mtile * NCHUNK) * ACH;

    #pragma unroll
    for (int s = 0; s < NSTAGE - 1; ++s) {
        load_stage(sbase + (uint32_t)s * STAGE_BYTES,
                   Asrc + (size_t)s * ACH, g_B + (size_t)s * BCH, tid);
        asm volatile("cp.async.commit_group;");
    }

    float acc[4][8][4];
    #pragma unroll
    for (int mt = 0; mt < 4; ++mt)
        #pragma unroll
        for (int nt = 0; nt < 8; ++nt)
            #pragma unroll
            for (int q = 0; q < 4; ++q) acc[mt][nt][q] = 0.f;

    for (int c = 0; c < NCHUNK; ++c) {
        if (c + NSTAGE - 1 < NCHUNK) {
            int cn = c + NSTAGE - 1;
            load_stage(sbase + (uint32_t)(cn & (NSTAGE - 1)) * STAGE_BYTES,
                       Asrc + (size_t)cn * ACH, g_B + (size_t)cn * BCH, tid);
            asm volatile("cp.async.commit_group;");
        }
        if (c <= NCHUNK - NSTAGE)      asm volatile("cp.async.wait_group 3;");
        else if (c == NCHUNK - 3)      asm volatile("cp.async.wait_group 2;");
        else if (c == NCHUNK - 2)      asm volatile("cp.async.wait_group 1;");
        else                           asm volatile("cp.async.wait_group 0;");
        __syncthreads();

        uint32_t st = sbase + (uint32_t)(c & (NSTAGE - 1)) * STAGE_BYTES;
        uint32_t Ah = st, Bh = st + ACH;

        #pragma unroll
        for (int k16 = 0; k16 < 4; ++k16) {
            int k0 = k16 * 16;
            uint32_t ah[4][4];
            #pragma unroll
            for (int mt = 0; mt < 4; ++mt)
                ldm_x4(a_addr(Ah, wm * 64 + mt * 16, k0, lane), ah[mt]);
            #pragma unroll
            for (int g = 0; g < 4; ++g) {
                uint32_t bh[4];
                ldm_x4(b_addr(Bh, wn * 64 + g * 16, k0, lane), bh);
                #pragma unroll
                for (int mt = 0; mt < 4; ++mt) {
                    mma16816(acc[mt][2 * g],     ah[mt], bh[0], bh[1]);
                    mma16816(acc[mt][2 * g + 1], ah[mt], bh[2], bh[3]);
                }
            }
        }
        __syncthreads();
    }

    // epilogue: bias + store
    int rbase = mtile * 128 + wm * 64 + (lane >> 2);
    int cbase = wn * 64 + (lane & 3) * 2;
    #pragma unroll
    for (int mt = 0; mt < 4; ++mt) {
        #pragma unroll
        for (int nt = 0; nt < 8; ++nt) {
            int row = rbase + mt * 16;
            int col = cbase + nt * 8;
            float b0 = bias[col], b1 = bias[col + 1];
            float2 v;
            v.x = acc[mt][nt][0] + b0; v.y = acc[mt][nt][1] + b1;
            *(float2*)(out + (size_t)row * D + col) = v;
            v.x = acc[mt][nt][2] + b0; v.y = acc[mt][nt][3] + b1;
            *(float2*)(out + (size_t)(row + 8) * D + col) = v;
        }
    }
}

// ---------------------------------------------------------------------------
extern "C" void kernel_launch(void* const* d_in, const int* in_sizes, int n_in,
                              void* d_out, int out_size) {
    const float* x     = (const float*)d_in[0];
    const float* comp  = (const float*)d_in[1];
    const float* basis = (const float*)d_in[2];
    const float* root  = (const float*)d_in[3];
    const float* bias  = (const float*)d_in[4];
    float* out = (float*)d_out;

    cudaFuncSetAttribute(gemm_hmma, cudaFuncAttributeMaxDynamicSharedMemorySize, GEMM_SMEM);

    prep<<<BATCH * PART + KC, 128>>>(x, basis, root);
    colsum_reduce<<<BATCH, 64>>>();
    build_z_pack<<<dim3(S / 16, BATCH), 256>>>(x, comp);
    gemm_hmma<<<MTILES, 256, GEMM_SMEM>>>(bias, out);
}